// round 6
// baseline (speedup 1.0000x reference)
#include <cuda_runtime.h>
#include <cuda_bf16.h>
#include <cstdint>

// SGC degree-2: out = A @ (A @ x)
// x: [N=100000, D=64] fp32, E = 3.2M, edge_index int32 [2,E] = [dst; src]
//
// CSR-build-once + gather SpMM.
// R6: gather pass rework — float4 lanes (16 lanes per row, 2 edges per warp
// iteration, unrolled x2 => 4 edges / 2x16B loads per thread in flight) to
// convert the latency-exposed R5 loop (~55% of L2 roofline) into an
// MLP-saturated one. Cross-half combine via shfl_xor(16), 128-bit row store.

#define N_NODES 100000
#define D 64
#define E_MAX 3200000
#define SCAN_T 1024

__device__ __align__(16) float g_tmp[N_NODES * D];
__device__ __align__(16) int2  g_edges[E_MAX];   // {src, w bits}
__device__ int g_cnt[N_NODES];
__device__ int g_ptr[N_NODES + 1];
__device__ int g_cur[N_NODES];

__global__ void zero_cnt()
{
    int i = blockIdx.x * blockDim.x + threadIdx.x;
    if (i < N_NODES) g_cnt[i] = 0;
}

__global__ void hist(const int* __restrict__ dst, int E)
{
    int e = blockIdx.x * blockDim.x + threadIdx.x;
    if (e < E) atomicAdd(&g_cnt[dst[e]], 1);
}

// Single-CTA exclusive scan over N_NODES counts -> g_ptr (+ cursor copy).
__global__ void scan_kernel(int E)
{
    __shared__ int s[SCAN_T];
    int tid = threadIdx.x;
    const int chunk = (N_NODES + SCAN_T - 1) / SCAN_T;
    int start = tid * chunk;
    int end   = start + chunk;
    if (end > N_NODES) end = N_NODES;
    if (start > N_NODES) start = N_NODES;

    int sum = 0;
    for (int i = start; i < end; i++) sum += g_cnt[i];
    s[tid] = sum;
    __syncthreads();

    for (int off = 1; off < SCAN_T; off <<= 1) {
        int v = 0;
        if (tid >= off) v = s[tid - off];
        __syncthreads();
        s[tid] += v;
        __syncthreads();
    }

    int run = s[tid] - sum;
    for (int i = start; i < end; i++) {
        g_ptr[i] = run;
        g_cur[i] = run;
        run += g_cnt[i];
    }
    if (tid == SCAN_T - 1) g_ptr[N_NODES] = s[SCAN_T - 1];
}

__global__ void fill(const int* __restrict__ dst,
                     const int* __restrict__ src,
                     const float* __restrict__ w, int E)
{
    int e = blockIdx.x * blockDim.x + threadIdx.x;
    if (e < E) {
        int slot = atomicAdd(&g_cur[dst[e]], 1);
        g_edges[slot] = make_int2(src[e], __float_as_int(w[e]));
    }
}

// Gather SpMM: 1 warp per dst row. 16 lanes span the 64-float row (float4
// per lane); the two half-warps take consecutive edges. Unrolled x2 -> 4
// edges in flight per warp iteration.
// PASS=0: xarg -> g_tmp.  PASS=1: g_tmp -> outarg.
template <int PASS>
__global__ void spmm_gather(const float* __restrict__ xarg,
                            float* __restrict__ outarg)
{
    int row = (int)(((long long)blockIdx.x * blockDim.x + threadIdx.x) >> 5);
    if (row >= N_NODES) return;
    int lane = threadIdx.x & 31;
    int half = lane >> 4;           // which edge of the pair
    int c    = (lane & 15) << 2;    // float4 column offset

    const float* __restrict__ xin = (PASS == 0) ? xarg : g_tmp;
    float* __restrict__ outp      = (PASS == 0) ? g_tmp : outarg;

    int beg = g_ptr[row];
    int end = g_ptr[row + 1];

    float a0 = 0.f, a1 = 0.f, a2 = 0.f, a3 = 0.f;

    int i = beg + half;             // this half-warp's edges: i, i+2, i+4, ...
    // unrolled: 2 edges per half-warp per iteration (4 per warp)
    for (; i + 2 < end; i += 4) {
        int2 ea = g_edges[i];
        int2 eb = g_edges[i + 2];
        float4 va = *reinterpret_cast<const float4*>(xin + (long long)ea.x * D + c);
        float4 vb = *reinterpret_cast<const float4*>(xin + (long long)eb.x * D + c);
        float wa = __int_as_float(ea.y);
        float wb = __int_as_float(eb.y);
        a0 += wa * va.x; a1 += wa * va.y; a2 += wa * va.z; a3 += wa * va.w;
        a0 += wb * vb.x; a1 += wb * vb.y; a2 += wb * vb.z; a3 += wb * vb.w;
    }
    for (; i < end; i += 2) {
        int2 e = g_edges[i];
        float4 v = *reinterpret_cast<const float4*>(xin + (long long)e.x * D + c);
        float wv = __int_as_float(e.y);
        a0 += wv * v.x; a1 += wv * v.y; a2 += wv * v.z; a3 += wv * v.w;
    }

    // combine the two half-warps (same output columns, different edges)
    a0 += __shfl_xor_sync(0xffffffffu, a0, 16);
    a1 += __shfl_xor_sync(0xffffffffu, a1, 16);
    a2 += __shfl_xor_sync(0xffffffffu, a2, 16);
    a3 += __shfl_xor_sync(0xffffffffu, a3, 16);

    if (half == 0)
        *reinterpret_cast<float4*>(outp + (long long)row * D + c) =
            make_float4(a0, a1, a2, a3);
}

extern "C" void kernel_launch(void* const* d_in, const int* in_sizes, int n_in,
                              void* d_out, int out_size)
{
    const float* features    = (const float*)d_in[0];   // [N, 64]
    const float* edge_weight = (const float*)d_in[1];   // [E]
    const int*   edge_index  = (const int*)d_in[2];     // [2, E] int32: dst, src
    // d_in[3] = degree (always 2 per setup_inputs)

    int E = in_sizes[1];
    const int* dst  = edge_index;
    const int* srcp = edge_index + E;
    float* out = (float*)d_out;

    const int T = 256;

    // --- build CSR (once, reused by both passes) ---
    zero_cnt<<<(N_NODES + T - 1) / T, T>>>();
    hist<<<(E + T - 1) / T, T>>>(dst, E);
    scan_kernel<<<1, SCAN_T>>>(E);
    fill<<<(E + T - 1) / T, T>>>(dst, srcp, edge_weight, E);

    // --- 2x gather SpMM (warp per row; 8 rows per 256-thread block) ---
    int rows_per_block = T / 32;
    int blocks = (N_NODES + rows_per_block - 1) / rows_per_block;
    spmm_gather<0><<<blocks, T>>>(features, out);
    spmm_gather<1><<<blocks, T>>>(features, out);
}

// round 7
// speedup vs baseline: 1.7230x; 1.7230x over previous
#include <cuda_runtime.h>
#include <cuda_bf16.h>
#include <cstdint>

// SGC degree-2: out = A @ (A @ x)
// x: [N=100000, D=64] fp32, E = 3.2M, edge_index int32 [2,E] = [dst; src]
//
// CSR-build-once + gather SpMM.
// R7: revert to R5 gather shape (float2 lanes, whole warp on one edge's row)
// but unroll 8 edges per iteration with a predicated 8-wide epilogue (no
// serial tail). Replace the single-CTA scan with a 3-phase parallel scan.

#define N_NODES 100000
#define D 64
#define E_MAX 3200000

#define SCAN_B 200      // phase-A/C CTAs
#define SCAN_TT 512     // threads per phase-A/C CTA (200*512 >= N)

__device__ __align__(16) float g_tmp[N_NODES * D];
__device__ __align__(16) int2  g_edges[E_MAX];   // {src, w bits}
__device__ int g_cnt[N_NODES];
__device__ int g_ptr[N_NODES + 1];
__device__ int g_cur[N_NODES];
__device__ int g_excl[SCAN_B * SCAN_TT];
__device__ int g_btot[SCAN_B];
__device__ int g_boff[SCAN_B];

__global__ void zero_cnt()
{
    int i = blockIdx.x * blockDim.x + threadIdx.x;
    if (i < N_NODES) g_cnt[i] = 0;
}

__global__ void hist(const int* __restrict__ dst, int E)
{
    int e = blockIdx.x * blockDim.x + threadIdx.x;
    if (e < E) atomicAdd(&g_cnt[dst[e]], 1);
}

// Phase A: per-block inclusive scan of 512 counts -> per-thread exclusive
// offsets (g_excl) + block totals (g_btot).
__global__ void scanA()
{
    __shared__ int s[SCAN_TT];
    int t = threadIdx.x;
    int i = blockIdx.x * SCAN_TT + t;
    int v = (i < N_NODES) ? g_cnt[i] : 0;
    s[t] = v;
    __syncthreads();
    for (int off = 1; off < SCAN_TT; off <<= 1) {
        int u = (t >= off) ? s[t - off] : 0;
        __syncthreads();
        s[t] += u;
        __syncthreads();
    }
    g_excl[i < N_NODES ? i : (SCAN_B * SCAN_TT - 1)] = 0; // no-op safety
    if (i < N_NODES) g_excl[i] = s[t] - v;
    if (t == SCAN_TT - 1) g_btot[blockIdx.x] = s[t];
}

// Phase B: single CTA scans the SCAN_B block totals -> g_boff; sets ptr[N].
__global__ void scanB(int E)
{
    __shared__ int s[256];
    int t = threadIdx.x;
    int v = (t < SCAN_B) ? g_btot[t] : 0;
    s[t] = v;
    __syncthreads();
    for (int off = 1; off < 256; off <<= 1) {
        int u = (t >= off) ? s[t - off] : 0;
        __syncthreads();
        s[t] += u;
        __syncthreads();
    }
    if (t < SCAN_B) g_boff[t] = s[t] - v;
    if (t == 0) g_ptr[N_NODES] = E;
}

// Phase C: distribute block offsets.
__global__ void scanC()
{
    int t = threadIdx.x;
    int i = blockIdx.x * SCAN_TT + t;
    if (i < N_NODES) {
        int p = g_excl[i] + g_boff[blockIdx.x];
        g_ptr[i] = p;
        g_cur[i] = p;
    }
}

__global__ void fill(const int* __restrict__ dst,
                     const int* __restrict__ src,
                     const float* __restrict__ w, int E)
{
    int e = blockIdx.x * blockDim.x + threadIdx.x;
    if (e < E) {
        int slot = atomicAdd(&g_cur[dst[e]], 1);
        g_edges[slot] = make_int2(src[e], __float_as_int(w[e]));
    }
}

// Gather SpMM: 1 warp per dst row; each lane owns 2 consecutive floats.
// 8 edges in flight per iteration, predicated (no serial tail).
// PASS=0: xarg -> g_tmp.  PASS=1: g_tmp -> outarg.
template <int PASS>
__global__ void spmm_gather(const float* __restrict__ xarg,
                            float* __restrict__ outarg)
{
    int row = (int)(((long long)blockIdx.x * blockDim.x + threadIdx.x) >> 5);
    if (row >= N_NODES) return;
    int lane = threadIdx.x & 31;
    int c = lane * 2;

    const float* __restrict__ xin = (PASS == 0) ? xarg : g_tmp;
    float* __restrict__ outp      = (PASS == 0) ? g_tmp : outarg;

    int beg = g_ptr[row];
    int end = g_ptr[row + 1];

    float a0 = 0.0f, a1 = 0.0f;

    for (int i = beg; i < end; i += 8) {
        int2   e[8];
        float2 v[8];
        #pragma unroll
        for (int j = 0; j < 8; j++) {
            bool p = (i + j) < end;
            e[j] = p ? g_edges[i + j] : make_int2(0, 0);
        }
        #pragma unroll
        for (int j = 0; j < 8; j++) {
            bool p = (i + j) < end;
            v[j] = p ? *reinterpret_cast<const float2*>(
                           xin + (long long)e[j].x * D + c)
                     : make_float2(0.f, 0.f);
        }
        #pragma unroll
        for (int j = 0; j < 8; j++) {
            float wv = __int_as_float(e[j].y);
            a0 += wv * v[j].x;
            a1 += wv * v[j].y;
        }
    }

    *reinterpret_cast<float2*>(outp + (long long)row * D + c) =
        make_float2(a0, a1);
}

extern "C" void kernel_launch(void* const* d_in, const int* in_sizes, int n_in,
                              void* d_out, int out_size)
{
    const float* features    = (const float*)d_in[0];   // [N, 64]
    const float* edge_weight = (const float*)d_in[1];   // [E]
    const int*   edge_index  = (const int*)d_in[2];     // [2, E] int32: dst, src
    // d_in[3] = degree (always 2 per setup_inputs)

    int E = in_sizes[1];
    const int* dst  = edge_index;
    const int* srcp = edge_index + E;
    float* out = (float*)d_out;

    const int T = 256;

    // --- build CSR (once, reused by both passes) ---
    zero_cnt<<<(N_NODES + T - 1) / T, T>>>();
    hist<<<(E + T - 1) / T, T>>>(dst, E);
    scanA<<<SCAN_B, SCAN_TT>>>();
    scanB<<<1, 256>>>(E);
    scanC<<<SCAN_B, SCAN_TT>>>();
    fill<<<(E + T - 1) / T, T>>>(dst, srcp, edge_weight, E);

    // --- 2x gather SpMM (warp per row; 8 rows per 256-thread block) ---
    int rows_per_block = T / 32;
    int blocks = (N_NODES + rows_per_block - 1) / rows_per_block;
    spmm_gather<0><<<blocks, T>>>(features, out);
    spmm_gather<1><<<blocks, T>>>(features, out);
}